// round 8
// baseline (speedup 1.0000x reference)
#include <cuda_runtime.h>
#include <math.h>
#include <stdint.h>

#define NUM_E   8
#define DIM     1024
#define HID     4096
#define TOKENS  8192
#define CAP     TOKENS
#define ROWS_T  (TOKENS * 2)

// ------------------------------------------------------------- scratch
static __device__ float g_h[(size_t)ROWS_T * HID];              // 268 MB
static __device__ float g_y[(size_t)ROWS_T * DIM];              // 64 MB
static __device__ float g_W1h[(size_t)NUM_E * DIM * HID];       // 134 MB
static __device__ float g_W1l[(size_t)NUM_E * DIM * HID];       // 134 MB
static __device__ float g_W2h[(size_t)NUM_E * HID * DIM];       // 134 MB
static __device__ float g_W2l[(size_t)NUM_E * HID * DIM];       // 134 MB
static __device__ int   g_rowmap[NUM_E * CAP];
static __device__ int   g_cnt[NUM_E];
static __device__ float g_topw[ROWS_T];

// ------------------------------------------------------------- helpers
__device__ __forceinline__ uint32_t hi_bits(float f) {
    return __float_as_uint(f) & 0xFFFFE000u;   // exactly tf32-representable
}
__device__ __forceinline__ uint32_t cvt_tf32(float f) {
    uint32_t u;
    asm("cvt.rna.tf32.f32 %0, %1;" : "=r"(u) : "f"(f));
    return u;
}
__device__ __forceinline__ uint32_t lo_bits(float f) {
    return cvt_tf32(f - __uint_as_float(hi_bits(f)));
}
__device__ __forceinline__ float gelu_exact(float v) {
    return 0.5f * v * (1.0f + erff(v * 0.7071067811865476f));
}
__device__ __forceinline__ void mma_tf32(float* c, const uint32_t* a, const uint32_t* b) {
    asm volatile(
        "mma.sync.aligned.m16n8k8.row.col.f32.tf32.tf32.f32 "
        "{%0,%1,%2,%3}, {%4,%5,%6,%7}, {%8,%9}, {%0,%1,%2,%3};"
        : "+f"(c[0]), "+f"(c[1]), "+f"(c[2]), "+f"(c[3])
        : "r"(a[0]), "r"(a[1]), "r"(a[2]), "r"(a[3]), "r"(b[0]), "r"(b[1]));
}

// ------------------------------------------------------------- router
__global__ void zero_cnt_kernel() {
    if (threadIdx.x < NUM_E) g_cnt[threadIdx.x] = 0;
}

__global__ __launch_bounds__(256) void router_kernel(
    const float* __restrict__ x, const float* __restrict__ Wr) {
    const int t = blockIdx.x;
    const int tid = threadIdx.x;
    const float4 xv = *(const float4*)(x + (size_t)t * DIM + tid * 4);
    float acc[NUM_E];
#pragma unroll
    for (int e = 0; e < NUM_E; e++) {
        const float4 wv = *(const float4*)(Wr + e * DIM + tid * 4);
        acc[e] = xv.x * wv.x + xv.y * wv.y + xv.z * wv.z + xv.w * wv.w;
    }
#pragma unroll
    for (int off = 16; off; off >>= 1)
#pragma unroll
        for (int e = 0; e < NUM_E; e++)
            acc[e] += __shfl_down_sync(0xffffffffu, acc[e], off);

    __shared__ float sred[8][NUM_E];
    const int wid = tid >> 5, lane = tid & 31;
    if (lane == 0)
#pragma unroll
        for (int e = 0; e < NUM_E; e++) sred[wid][e] = acc[e];
    __syncthreads();

    if (tid == 0) {
        float lg[NUM_E];
#pragma unroll
        for (int e = 0; e < NUM_E; e++) {
            float s = 0.f;
#pragma unroll
            for (int w = 0; w < 8; w++) s += sred[w][e];
            lg[e] = s;
        }
        float mx = lg[0];
#pragma unroll
        for (int e = 1; e < NUM_E; e++) mx = fmaxf(mx, lg[e]);
        float p[NUM_E], psum = 0.f;
#pragma unroll
        for (int e = 0; e < NUM_E; e++) { p[e] = expf(lg[e] - mx); psum += p[e]; }
        const float inv = 1.0f / psum;
#pragma unroll
        for (int e = 0; e < NUM_E; e++) p[e] *= inv;

        int i1 = 0;
#pragma unroll
        for (int e = 1; e < NUM_E; e++) if (p[e] > p[i1]) i1 = e;
        int i2 = -1;
#pragma unroll
        for (int e = 0; e < NUM_E; e++) {
            if (e == i1) continue;
            if (i2 < 0 || p[e] > p[i2]) i2 = e;
        }
        int p1 = atomicAdd(&g_cnt[i1], 1);
        g_rowmap[i1 * CAP + p1] = t * 2;
        int p2 = atomicAdd(&g_cnt[i2], 1);
        g_rowmap[i2 * CAP + p2] = t * 2 + 1;
        g_topw[t * 2]     = p[i1];
        g_topw[t * 2 + 1] = p[i2];
    }
}

// ------------------------------------------------------------- W split (fp32 -> tf32 hi/lo)
// Destinations are device globals referenced FROM DEVICE CODE (host cannot
// take the address of a __device__ array — that was the R6/R7 failure).
__device__ __forceinline__ void split_elem(const float4 v, float4& h, float4& l) {
    h.x = __uint_as_float(hi_bits(v.x)); l.x = __uint_as_float(lo_bits(v.x));
    h.y = __uint_as_float(hi_bits(v.y)); l.y = __uint_as_float(lo_bits(v.y));
    h.z = __uint_as_float(hi_bits(v.z)); l.z = __uint_as_float(lo_bits(v.z));
    h.w = __uint_as_float(hi_bits(v.w)); l.w = __uint_as_float(lo_bits(v.w));
}
__global__ __launch_bounds__(256) void split_w1_kernel(const float* __restrict__ src) {
    const int i = blockIdx.x * 256 + threadIdx.x;           // n4 = 8.39M, exact grid
    const float4 v = ((const float4*)src)[i];
    float4 h, l;
    split_elem(v, h, l);
    ((float4*)g_W1h)[i] = h;
    ((float4*)g_W1l)[i] = l;
}
__global__ __launch_bounds__(256) void split_w2_kernel(const float* __restrict__ src) {
    const int i = blockIdx.x * 256 + threadIdx.x;
    const float4 v = ((const float4*)src)[i];
    float4 h, l;
    split_elem(v, h, l);
    ((float4*)g_W2h)[i] = h;
    ((float4*)g_W2l)[i] = l;
}

// ------------------------------------------------------------- mma.sync grouped GEMM
// block 128x256, BK=8; 8 warps of 64x64; 3xTF32 split (ah*bh + al*bh + ah*bl)
#define BM 128
#define BN 256
#define BK 8
#define SA_PITCH 12                      // words: banks (12*lr+lc) mod 32 all distinct
#define SB_PITCH 264                     // words: 264 mod 32 = 8 -> (8*lc+lr) distinct
#define A_WORDS (BM * SA_PITCH)          // 1536
#define B_WORDS (BK * SB_PITCH)          // 2112
#define STAGE_WORDS (A_WORDS + B_WORDS)  // 3648
#define SMEM_GEMM (2 * STAGE_WORDS * 4)  // 29184 bytes  (< 48 KB: no opt-in needed)

template <int KDIM, int NDIM, bool DO_GELU, bool GATHER>
__device__ __forceinline__ void gemm_mma_body(
    const float* __restrict__ A, const float* __restrict__ Bh,
    const float* __restrict__ Bl, const float* __restrict__ bias,
    float* __restrict__ Cout) {
    extern __shared__ uint32_t smem[];
    const int e = blockIdx.z;
    const int cnt = g_cnt[e];
    const int m0 = blockIdx.x * BM;
    if (m0 >= cnt) return;
    const int n0 = blockIdx.y * BN;
    const int tid = threadIdx.x;
    const int wid = tid >> 5, lane = tid & 31;
    const int wm = wid & 1, wn = wid >> 1;          // warp tile (wm*64, wn*64)
    const int lr = lane >> 2, lc = lane & 3;

    // ---- A loader: 2 threads per row, 4 floats each (row fully covered: 8)
    const int am = tid >> 1, ah = tid & 1;
    const int gm = m0 + am;
    const int rA = g_rowmap[e * CAP + (gm < cnt ? gm : 0)];
    const float* pa = A + (size_t)(GATHER ? (rA >> 1) : rA) * KDIM + ah * 4;
    const uint32_t offA = am * SA_PITCH + ah * 4;

    // ---- B loader: 32 threads per k-row, 2 float4 each (cols bc, bc+128)
    const int bk = tid >> 5, bc = (tid & 31) * 4;
    const uint32_t offB = A_WORDS + bk * SB_PITCH + bc;
    const size_t b_off = (size_t)e * KDIM * NDIM + (size_t)bk * NDIM + n0 + bc;

    const int CHUNKS = 3 * (KDIM / BK);

    float c[4][8][4];
#pragma unroll
    for (int mt = 0; mt < 4; mt++)
#pragma unroll
        for (int nt = 0; nt < 8; nt++)
#pragma unroll
            for (int j = 0; j < 4; j++) c[mt][nt][j] = 0.f;

    // ---- prefetch chunk 0 into registers (kb=0, term=0 -> A hi at STS, B=Bh)
    float4 av = *(const float4*)(pa);
    float4 bv0 = *(const float4*)(Bh + b_off);
    float4 bv1 = *(const float4*)(Bh + b_off + 128);

    for (int ch = 0; ch < CHUNKS; ch++) {
        const int buf = ch & 1;
        const int term = ch % 3;
        uint32_t* sbase = smem + buf * STAGE_WORDS;

        // ---- STS current chunk (A converted hi/lo by term; B already split)
        {
            uint4 aw;
            if (term == 1) {
                aw.x = lo_bits(av.x); aw.y = lo_bits(av.y);
                aw.z = lo_bits(av.z); aw.w = lo_bits(av.w);
            } else {
                aw.x = hi_bits(av.x); aw.y = hi_bits(av.y);
                aw.z = hi_bits(av.z); aw.w = hi_bits(av.w);
            }
            *(uint4*)(sbase + offA) = aw;
            *(float4*)(sbase + offB) = bv0;
            *(float4*)(sbase + offB + 128) = bv1;
        }
        __syncthreads();

        // ---- prefetch next chunk (gmem -> regs, overlaps compute)
        if (ch + 1 < CHUNKS) {
            const int cn = ch + 1;
            const int kb = cn / 3;
            const int nt_ = cn % 3;
            av = *(const float4*)(pa + kb * BK);
            const float* bsrc = (nt_ < 2 ? Bh : Bl) + b_off + (size_t)kb * BK * NDIM;
            bv0 = *(const float4*)(bsrc);
            bv1 = *(const float4*)(bsrc + 128);
        }

        // ---- compute on buf (one k8 step: 4x8 mma grid)
        const uint32_t* sA = smem + buf * STAGE_WORDS;
        const uint32_t* sB = sA + A_WORDS;
        uint32_t a[4][4], b[8][2];
#pragma unroll
        for (int mt = 0; mt < 4; mt++) {
            const uint32_t* p = sA + (wm * 64 + mt * 16 + lr) * SA_PITCH + lc;
            a[mt][0] = p[0];
            a[mt][1] = p[8 * SA_PITCH];
            a[mt][2] = p[4];
            a[mt][3] = p[8 * SA_PITCH + 4];
        }
#pragma unroll
        for (int nt = 0; nt < 8; nt++) {
            const uint32_t* p = sB + lc * SB_PITCH + wn * 64 + nt * 8 + lr;
            b[nt][0] = p[0];
            b[nt][1] = p[4 * SB_PITCH];
        }
#pragma unroll
        for (int mt = 0; mt < 4; mt++)
#pragma unroll
            for (int nt = 0; nt < 8; nt++)
                mma_tf32(c[mt][nt], a[mt], b[nt]);
    }

    // ---- epilogue: bias (+GELU) + rowmap scatter
    const int lc2 = (lane & 3) * 2;
    const float* pbias = bias + (size_t)e * NDIM + n0 + wn * 64;
    float2 bv[8];
#pragma unroll
    for (int nt = 0; nt < 8; nt++)
        bv[nt] = *(const float2*)(pbias + nt * 8 + lc2);

#pragma unroll
    for (int mt = 0; mt < 4; mt++) {
#pragma unroll
        for (int half = 0; half < 2; half++) {
            const int gmr = m0 + wm * 64 + mt * 16 + half * 8 + lr;
            if (gmr >= cnt) continue;
            const int r = g_rowmap[e * CAP + gmr];
            float* pr = Cout + (size_t)r * NDIM + n0 + wn * 64;
#pragma unroll
            for (int nt = 0; nt < 8; nt++) {
                float x0 = c[mt][nt][half * 2 + 0] + bv[nt].x;
                float x1 = c[mt][nt][half * 2 + 1] + bv[nt].y;
                if (DO_GELU) { x0 = gelu_exact(x0); x1 = gelu_exact(x1); }
                *(float2*)(pr + nt * 8 + lc2) = make_float2(x0, x1);
            }
        }
    }
}

__global__ __launch_bounds__(256, 1) void fc1_mma_kernel(
    const float* __restrict__ x, const float* __restrict__ b1) {
    gemm_mma_body<DIM, HID, true, true>(x, g_W1h, g_W1l, b1, g_h);
}
__global__ __launch_bounds__(256, 1) void fc2_mma_kernel(const float* __restrict__ b2) {
    gemm_mma_body<HID, DIM, false, false>(g_h, g_W2h, g_W2l, b2, g_y);
}

// ------------------------------------------------------------- combine
__global__ __launch_bounds__(256) void combine_kernel(float* __restrict__ out) {
    const int t = blockIdx.x;
    const int d = threadIdx.x * 4;
    const float w0 = g_topw[2 * t];
    const float w1 = g_topw[2 * t + 1];
    const float4 y0 = *(const float4*)&g_y[(size_t)(2 * t) * DIM + d];
    const float4 y1 = *(const float4*)&g_y[(size_t)(2 * t + 1) * DIM + d];
    float4 o;
    o.x = w0 * y0.x + w1 * y1.x;
    o.y = w0 * y0.y + w1 * y1.y;
    o.z = w0 * y0.z + w1 * y1.z;
    o.w = w0 * y0.w + w1 * y1.w;
    *(float4*)(out + (size_t)t * DIM + d) = o;
}

// ------------------------------------------------------------- launch
extern "C" void kernel_launch(void* const* d_in, const int* in_sizes, int n_in,
                              void* d_out, int out_size) {
    const float* x  = (const float*)d_in[0];
    const float* Wr = (const float*)d_in[1];
    const float* W1 = (const float*)d_in[2];
    const float* b1 = (const float*)d_in[3];
    const float* W2 = (const float*)d_in[4];
    const float* b2 = (const float*)d_in[5];
    float* out = (float*)d_out;
    (void)in_sizes; (void)n_in; (void)out_size;

    zero_cnt_kernel<<<1, 32>>>();
    router_kernel<<<TOKENS, 256>>>(x, Wr);
    split_w1_kernel<<<NUM_E * DIM * HID / 4 / 256, 256>>>(W1);
    split_w2_kernel<<<NUM_E * HID * DIM / 4 / 256, 256>>>(W2);
    fc1_mma_kernel<<<dim3(CAP / BM, HID / BN, NUM_E), 256, SMEM_GEMM>>>(x, b1);
    fc2_mma_kernel<<<dim3(CAP / BM, DIM / BN, NUM_E), 256, SMEM_GEMM>>>(b2);
    combine_kernel<<<TOKENS, 256>>>(out);
}

// round 9
// speedup vs baseline: 2.2830x; 2.2830x over previous
#include <cuda_runtime.h>
#include <math.h>
#include <stdint.h>

#define NUM_E   8
#define DIM     1024
#define HID     4096
#define TOKENS  8192
#define CAP     TOKENS
#define ROWS_T  (TOKENS * 2)

// ------------------------------------------------------------- scratch
static __device__ float g_h[(size_t)ROWS_T * HID];              // 268 MB
static __device__ float g_y[(size_t)ROWS_T * DIM];              // 64 MB
static __device__ float g_W1t[(size_t)NUM_E * DIM * HID];       // 134 MB (tf32-rounded)
static __device__ float g_W2t[(size_t)NUM_E * HID * DIM];       // 134 MB (tf32-rounded)
static __device__ int   g_rowmap[NUM_E * CAP];
static __device__ int   g_cnt[NUM_E];
static __device__ float g_topw[ROWS_T];

// ------------------------------------------------------------- helpers
__device__ __forceinline__ uint32_t hi_bits(float f) {
    return __float_as_uint(f) & 0xFFFFE000u;   // exactly tf32-representable
}
__device__ __forceinline__ uint32_t cvt_tf32(float f) {
    uint32_t u;
    asm("cvt.rna.tf32.f32 %0, %1;" : "=r"(u) : "f"(f));
    return u;
}
__device__ __forceinline__ uint32_t lo_bits(float f) {
    return cvt_tf32(f - __uint_as_float(hi_bits(f)));
}
__device__ __forceinline__ float gelu_exact(float v) {
    return 0.5f * v * (1.0f + erff(v * 0.7071067811865476f));
}
__device__ __forceinline__ void mma_tf32(float* c, const uint32_t* a, const uint32_t* b) {
    asm volatile(
        "mma.sync.aligned.m16n8k8.row.col.f32.tf32.tf32.f32 "
        "{%0,%1,%2,%3}, {%4,%5,%6,%7}, {%8,%9}, {%0,%1,%2,%3};"
        : "+f"(c[0]), "+f"(c[1]), "+f"(c[2]), "+f"(c[3])
        : "r"(a[0]), "r"(a[1]), "r"(a[2]), "r"(a[3]), "r"(b[0]), "r"(b[1]));
}

// ------------------------------------------------------------- router
__global__ void zero_cnt_kernel() {
    if (threadIdx.x < NUM_E) g_cnt[threadIdx.x] = 0;
}

__global__ __launch_bounds__(256) void router_kernel(
    const float* __restrict__ x, const float* __restrict__ Wr) {
    const int t = blockIdx.x;
    const int tid = threadIdx.x;
    const float4 xv = *(const float4*)(x + (size_t)t * DIM + tid * 4);
    float acc[NUM_E];
#pragma unroll
    for (int e = 0; e < NUM_E; e++) {
        const float4 wv = *(const float4*)(Wr + e * DIM + tid * 4);
        acc[e] = xv.x * wv.x + xv.y * wv.y + xv.z * wv.z + xv.w * wv.w;
    }
#pragma unroll
    for (int off = 16; off; off >>= 1)
#pragma unroll
        for (int e = 0; e < NUM_E; e++)
            acc[e] += __shfl_down_sync(0xffffffffu, acc[e], off);

    __shared__ float sred[8][NUM_E];
    const int wid = tid >> 5, lane = tid & 31;
    if (lane == 0)
#pragma unroll
        for (int e = 0; e < NUM_E; e++) sred[wid][e] = acc[e];
    __syncthreads();

    if (tid == 0) {
        float lg[NUM_E];
#pragma unroll
        for (int e = 0; e < NUM_E; e++) {
            float s = 0.f;
#pragma unroll
            for (int w = 0; w < 8; w++) s += sred[w][e];
            lg[e] = s;
        }
        float mx = lg[0];
#pragma unroll
        for (int e = 1; e < NUM_E; e++) mx = fmaxf(mx, lg[e]);
        float p[NUM_E], psum = 0.f;
#pragma unroll
        for (int e = 0; e < NUM_E; e++) { p[e] = expf(lg[e] - mx); psum += p[e]; }
        const float inv = 1.0f / psum;
#pragma unroll
        for (int e = 0; e < NUM_E; e++) p[e] *= inv;

        int i1 = 0;
#pragma unroll
        for (int e = 1; e < NUM_E; e++) if (p[e] > p[i1]) i1 = e;
        int i2 = -1;
#pragma unroll
        for (int e = 0; e < NUM_E; e++) {
            if (e == i1) continue;
            if (i2 < 0 || p[e] > p[i2]) i2 = e;
        }
        int p1 = atomicAdd(&g_cnt[i1], 1);
        g_rowmap[i1 * CAP + p1] = t * 2;
        int p2 = atomicAdd(&g_cnt[i2], 1);
        g_rowmap[i2 * CAP + p2] = t * 2 + 1;
        g_topw[t * 2]     = p[i1];
        g_topw[t * 2 + 1] = p[i2];
    }
}

// ------------------------------------------------------------- W round (fp32 -> tf32, rna)
__global__ __launch_bounds__(256) void round_w1_kernel(const float* __restrict__ src) {
    const int i = blockIdx.x * 256 + threadIdx.x;
    const float4 v = ((const float4*)src)[i];
    uint4 r;
    r.x = cvt_tf32(v.x); r.y = cvt_tf32(v.y);
    r.z = cvt_tf32(v.z); r.w = cvt_tf32(v.w);
    ((uint4*)g_W1t)[i] = r;
}
__global__ __launch_bounds__(256) void round_w2_kernel(const float* __restrict__ src) {
    const int i = blockIdx.x * 256 + threadIdx.x;
    const float4 v = ((const float4*)src)[i];
    uint4 r;
    r.x = cvt_tf32(v.x); r.y = cvt_tf32(v.y);
    r.z = cvt_tf32(v.z); r.w = cvt_tf32(v.w);
    ((uint4*)g_W2t)[i] = r;
}

// ------------------------------------------------------------- mma.sync grouped GEMM
// block 128x256; 8 warps of 64x64; per-k8 epoch: Ah,Al,B tiles in smem,
// 2 passes (ah*b, al*b). B pre-rounded tf32 in gmem.
#define BM 128
#define BN 256
#define BK 8
#define SA_PITCH 12                      // (12*lr+lc) mod 32 all distinct
#define SB_PITCH 264                     // 264 mod 32 = 8 -> (8*lc+lr) distinct
#define A_WORDS (BM * SA_PITCH)          // 1536 (per A tile; Ah + Al = 3072)
#define B_WORDS (BK * SB_PITCH)          // 2112
#define STAGE_WORDS (2 * A_WORDS + B_WORDS)   // 5184
#define SMEM_GEMM (2 * STAGE_WORDS * 4)       // 41472 bytes (< 48 KB)

template <int KDIM, int NDIM, bool DO_GELU, bool GATHER>
__device__ __forceinline__ void gemm_mma_body(
    const float* __restrict__ A, const float* __restrict__ Bt,
    const float* __restrict__ bias, float* __restrict__ Cout) {
    extern __shared__ uint32_t smem[];
    const int e = blockIdx.z;
    const int cnt = g_cnt[e];
    const int m0 = blockIdx.x * BM;
    if (m0 >= cnt) return;
    const int n0 = blockIdx.y * BN;
    const int tid = threadIdx.x;
    const int wid = tid >> 5, lane = tid & 31;
    const int wm = wid & 1, wn = wid >> 1;          // warp tile (wm*64, wn*64)
    const int lr = lane >> 2, lc = lane & 3;

    // ---- A loader: 2 threads per row, 4 floats each
    const int am = tid >> 1, ah = tid & 1;
    const int gm = m0 + am;
    const int rA = g_rowmap[e * CAP + (gm < cnt ? gm : 0)];
    const float* pa = A + (size_t)(GATHER ? (rA >> 1) : rA) * KDIM + ah * 4;
    const uint32_t offAh = am * SA_PITCH + ah * 4;
    const uint32_t offAl = offAh + A_WORDS;

    // ---- B loader: 32 threads per k-row, 2 float4 each (cols bc, bc+128)
    const int bk = tid >> 5, bc = (tid & 31) * 4;
    const uint32_t offB = 2 * A_WORDS + bk * SB_PITCH + bc;
    const float* pb = Bt + (size_t)e * KDIM * NDIM + (size_t)bk * NDIM + n0 + bc;

    const int KB = KDIM / BK;

    float c[4][8][4];
#pragma unroll
    for (int mt = 0; mt < 4; mt++)
#pragma unroll
        for (int nt = 0; nt < 8; nt++)
#pragma unroll
            for (int j = 0; j < 4; j++) c[mt][nt][j] = 0.f;

    // ---- prefetch epoch 0
    float4 av  = *(const float4*)(pa);
    float4 bv0 = *(const float4*)(pb);
    float4 bv1 = *(const float4*)(pb + 128);

    for (int kb = 0; kb < KB; kb++) {
        const int buf = kb & 1;
        uint32_t* sbase = smem + buf * STAGE_WORDS;

        // ---- STS: A split into hi+lo tiles (one LDG -> two STS); B raw tf32
        {
            uint4 hh, ll;
            hh.x = hi_bits(av.x); hh.y = hi_bits(av.y);
            hh.z = hi_bits(av.z); hh.w = hi_bits(av.w);
            ll.x = lo_bits(av.x); ll.y = lo_bits(av.y);
            ll.z = lo_bits(av.z); ll.w = lo_bits(av.w);
            *(uint4*)(sbase + offAh) = hh;
            *(uint4*)(sbase + offAl) = ll;
            *(float4*)(sbase + offB) = bv0;
            *(float4*)(sbase + offB + 128) = bv1;
        }
        __syncthreads();

        // ---- prefetch next epoch (overlaps the 64-MMA compute window)
        if (kb + 1 < KB) {
            av = *(const float4*)(pa + (kb + 1) * BK);
            const float* pbn = pb + (size_t)(kb + 1) * BK * NDIM;
            bv0 = *(const float4*)(pbn);
            bv1 = *(const float4*)(pbn + 128);
        }

        // ---- compute: b-frags loaded once, reused across both passes
        const uint32_t* st = smem + buf * STAGE_WORDS;
        const uint32_t* sB = st + 2 * A_WORDS;
        uint32_t b[8][2];
#pragma unroll
        for (int nt = 0; nt < 8; nt++) {
            const uint32_t* p = sB + lc * SB_PITCH + wn * 64 + nt * 8 + lr;
            b[nt][0] = p[0];
            b[nt][1] = p[4 * SB_PITCH];
        }
#pragma unroll
        for (int pass = 0; pass < 2; pass++) {
            const uint32_t* sA = st + pass * A_WORDS;
            uint32_t a[4][4];
#pragma unroll
            for (int mt = 0; mt < 4; mt++) {
                const uint32_t* p = sA + (wm * 64 + mt * 16 + lr) * SA_PITCH + lc;
                a[mt][0] = p[0];
                a[mt][1] = p[8 * SA_PITCH];
                a[mt][2] = p[4];
                a[mt][3] = p[8 * SA_PITCH + 4];
            }
#pragma unroll
            for (int mt = 0; mt < 4; mt++)
#pragma unroll
                for (int nt = 0; nt < 8; nt++)
                    mma_tf32(c[mt][nt], a[mt], b[nt]);
        }
    }

    // ---- epilogue: bias (+GELU) + rowmap scatter
    const int lc2 = (lane & 3) * 2;
    const float* pbias = bias + (size_t)e * NDIM + n0 + wn * 64;
    float2 bv[8];
#pragma unroll
    for (int nt = 0; nt < 8; nt++)
        bv[nt] = *(const float2*)(pbias + nt * 8 + lc2);

#pragma unroll
    for (int mt = 0; mt < 4; mt++) {
#pragma unroll
        for (int half = 0; half < 2; half++) {
            const int gmr = m0 + wm * 64 + mt * 16 + half * 8 + lr;
            if (gmr >= cnt) continue;
            const int r = g_rowmap[e * CAP + gmr];
            float* pr = Cout + (size_t)r * NDIM + n0 + wn * 64;
#pragma unroll
            for (int nt = 0; nt < 8; nt++) {
                float x0 = c[mt][nt][half * 2 + 0] + bv[nt].x;
                float x1 = c[mt][nt][half * 2 + 1] + bv[nt].y;
                if (DO_GELU) { x0 = gelu_exact(x0); x1 = gelu_exact(x1); }
                *(float2*)(pr + nt * 8 + lc2) = make_float2(x0, x1);
            }
        }
    }
}

__global__ __launch_bounds__(256, 1) void fc1_mma_kernel(
    const float* __restrict__ x, const float* __restrict__ b1) {
    gemm_mma_body<DIM, HID, true, true>(x, g_W1t, b1, g_h);
}
__global__ __launch_bounds__(256, 1) void fc2_mma_kernel(const float* __restrict__ b2) {
    gemm_mma_body<HID, DIM, false, false>(g_h, g_W2t, b2, g_y);
}

// ------------------------------------------------------------- combine
__global__ __launch_bounds__(256) void combine_kernel(float* __restrict__ out) {
    const int t = blockIdx.x;
    const int d = threadIdx.x * 4;
    const float w0 = g_topw[2 * t];
    const float w1 = g_topw[2 * t + 1];
    const float4 y0 = *(const float4*)&g_y[(size_t)(2 * t) * DIM + d];
    const float4 y1 = *(const float4*)&g_y[(size_t)(2 * t + 1) * DIM + d];
    float4 o;
    o.x = w0 * y0.x + w1 * y1.x;
    o.y = w0 * y0.y + w1 * y1.y;
    o.z = w0 * y0.z + w1 * y1.z;
    o.w = w0 * y0.w + w1 * y1.w;
    *(float4*)(out + (size_t)t * DIM + d) = o;
}

// ------------------------------------------------------------- launch
extern "C" void kernel_launch(void* const* d_in, const int* in_sizes, int n_in,
                              void* d_out, int out_size) {
    const float* x  = (const float*)d_in[0];
    const float* Wr = (const float*)d_in[1];
    const float* W1 = (const float*)d_in[2];
    const float* b1 = (const float*)d_in[3];
    const float* W2 = (const float*)d_in[4];
    const float* b2 = (const float*)d_in[5];
    float* out = (float*)d_out;
    (void)in_sizes; (void)n_in; (void)out_size;

    zero_cnt_kernel<<<1, 32>>>();
    router_kernel<<<TOKENS, 256>>>(x, Wr);
    round_w1_kernel<<<NUM_E * DIM * HID / 4 / 256, 256>>>(W1);
    round_w2_kernel<<<NUM_E * HID * DIM / 4 / 256, 256>>>(W2);
    fc1_mma_kernel<<<dim3(CAP / BM, HID / BN, NUM_E), 256, SMEM_GEMM>>>(x, b1);
    fc2_mma_kernel<<<dim3(CAP / BM, DIM / BN, NUM_E), 256, SMEM_GEMM>>>(b2);
    combine_kernel<<<TOKENS, 256>>>(out);
}